// round 3
// baseline (speedup 1.0000x reference)
#include <cuda_runtime.h>
#include <cuda_bf16.h>
#include <cstdint>

#define VOCAB   50257
#define VPAD    50304        /* 393 * 128 */
#define NEMBD   768
#define NROWS   8192
#define SEQLEN  1024
#define NSPLIT  9
#define NCHUNK  12           /* 768 / 64 */

#define SMEM_A_OFF 0
#define SMEM_B_OFF (NCHUNK * 16384)             /* 196608 */
#define SMEM_BYTES (SMEM_B_OFF + 2 * 16384)     /* 229376 <= 232448 */

// ---------------- device scratch ----------------
__device__ __align__(256) __nv_bfloat16 g_X[(size_t)NROWS * NEMBD];   // gelu(wte+wpe), bf16
__device__ __align__(256) __nv_bfloat16 g_W[(size_t)VPAD * NEMBD];    // W bf16, zero-padded
__device__ float g_pmax[NSPLIT][2][NROWS];    // per (split, wn-half) partial max
__device__ float g_psum[NSPLIT][2][NROWS];    // per (split, wn-half) partial sum-exp
__device__ float g_ll[NROWS];

// ---------------- helpers (sm_80-era PTX only; no 'a'-gated features) ----------------
__device__ __forceinline__ uint32_t smem_u32(const void* p) {
    uint32_t a;
    asm("{ .reg .u64 t; cvta.to.shared.u64 t, %1; cvt.u32.u64 %0, t; }" : "=r"(a) : "l"(p));
    return a;
}
__device__ __forceinline__ void cp_async16(uint32_t dst, const void* src) {
    asm volatile("cp.async.cg.shared.global [%0], [%1], 16;" :: "r"(dst), "l"(src));
}
__device__ __forceinline__ void cp_commit() {
    asm volatile("cp.async.commit_group;" ::: "memory");
}
template <int N>
__device__ __forceinline__ void cp_wait() {
    asm volatile("cp.async.wait_group %0;" :: "n"(N) : "memory");
}
__device__ __forceinline__ void ldsm_x4(uint32_t (&r)[4], uint32_t addr) {
    asm volatile("ldmatrix.sync.aligned.m8n8.x4.shared.b16 {%0,%1,%2,%3}, [%4];"
                 : "=r"(r[0]), "=r"(r[1]), "=r"(r[2]), "=r"(r[3]) : "r"(addr));
}
__device__ __forceinline__ void mma16816(float* c, const uint32_t* a, const uint32_t* b) {
    asm volatile(
        "mma.sync.aligned.m16n8k16.row.col.f32.bf16.bf16.f32 "
        "{%0,%1,%2,%3}, {%4,%5,%6,%7}, {%8,%9}, {%0,%1,%2,%3};"
        : "+f"(c[0]), "+f"(c[1]), "+f"(c[2]), "+f"(c[3])
        : "r"(a[0]), "r"(a[1]), "r"(a[2]), "r"(a[3]), "r"(b[0]), "r"(b[1]));
}
__device__ __forceinline__ uint32_t swz(uint32_t bo) { return bo ^ ((bo >> 3) & 0x70u); }

// ---------------- kernel 1: x = gelu(wte[tok] + wpe[pos]) -> bf16 ----------------
__global__ void prep_x_kernel(const int* __restrict__ data, const float* __restrict__ wte,
                              const float* __restrict__ wpe) {
    int idx = blockIdx.x * blockDim.x + threadIdx.x;
    if (idx >= NROWS * (NEMBD / 4)) return;
    int row = idx / (NEMBD / 4);
    int c4  = idx % (NEMBD / 4);
    int tok = data[row];
    int pos = row & (SEQLEN - 1);
    float4 a = *reinterpret_cast<const float4*>(wte + (size_t)tok * NEMBD + c4 * 4);
    float4 p = *reinterpret_cast<const float4*>(wpe + (size_t)pos * NEMBD + c4 * 4);
    const float K0 = 0.7978845608028654f, K1 = 0.044715f;
    float v[4] = {a.x + p.x, a.y + p.y, a.z + p.z, a.w + p.w};
    float g[4];
#pragma unroll
    for (int i = 0; i < 4; i++) {
        float x = v[i];
        g[i] = 0.5f * x * (1.0f + tanhf(K0 * (x + K1 * x * x * x)));
    }
    __nv_bfloat162* dst = reinterpret_cast<__nv_bfloat162*>(&g_X[(size_t)row * NEMBD + c4 * 4]);
    dst[0] = __floats2bfloat162_rn(g[0], g[1]);
    dst[1] = __floats2bfloat162_rn(g[2], g[3]);
}

// ---------------- kernel 2: W fp32 -> bf16 (zero-padded rows) ----------------
__global__ void conv_w_kernel(const float* __restrict__ W) {
    int idx = blockIdx.x * blockDim.x + threadIdx.x;
    if (idx >= VPAD * (NEMBD / 4)) return;
    int v  = idx / (NEMBD / 4);
    int c4 = idx % (NEMBD / 4);
    __nv_bfloat162 r0, r1;
    if (v < VOCAB) {
        float4 w = *reinterpret_cast<const float4*>(W + (size_t)v * NEMBD + c4 * 4);
        r0 = __floats2bfloat162_rn(w.x, w.y);
        r1 = __floats2bfloat162_rn(w.z, w.w);
    } else {
        r0 = __floats2bfloat162_rn(0.f, 0.f);
        r1 = r0;
    }
    __nv_bfloat162* dst = reinterpret_cast<__nv_bfloat162*>(&g_W[(size_t)v * NEMBD + c4 * 4]);
    dst[0] = r0;
    dst[1] = r1;
}

// ---------------- kernel 3: fused GEMM (mma.sync) + online logsumexp ----------------
// 256 threads = 8 warps in a 4(M) x 2(N) grid; warp tile 32x64; CTA tile 128x128.
// A (128x768) resident in SMEM; B (128x64 per chunk) double-buffered via cp.async.
__global__ void __launch_bounds__(256, 1)
gemm_lse_kernel() {
    extern __shared__ char smem[];
    const uint32_t smem_base = smem_u32(smem);
    const int tid  = threadIdx.x;
    const int lane = tid & 31;
    const int wid  = tid >> 5;
    const int wm   = wid >> 1;          // 0..3 : warp M index
    const int wn   = wid & 1;           // 0..1 : warp N index
    const int s    = blockIdx.x;        // vocab split
    const int m0   = blockIdx.y * 128;  // row tile base

    // ---- cp.async thread mapping: row = rb + j*32, 16B segment = seg ----
    const int rb  = tid >> 3;           // 0..31
    const int seg = tid & 7;            // 0..7

    // ---- load resident A: 12 chunks of 128x64 bf16, SW128-swizzled ----
#pragma unroll 1
    for (int kk = 0; kk < NCHUNK; kk++) {
        uint32_t abase = smem_base + SMEM_A_OFF + kk * 16384;
#pragma unroll
        for (int j = 0; j < 4; j++) {
            int r = rb + j * 32;
            uint32_t bo = (uint32_t)r * 128u + (uint32_t)seg * 16u;
            cp_async16(abase + swz(bo),
                       &g_X[(size_t)(m0 + r) * NEMBD + kk * 64 + seg * 8]);
        }
    }
    cp_commit();
    cp_wait<0>();
    __syncthreads();

    // ---- ldmatrix per-lane address components ----
    const int quad = lane >> 3;         // 0..3
    const int lrow = lane & 7;
    // A frag (16x16): quad0: m0..7/k0-7, quad1: m8..15/k0-7, quad2: m0..7/k8-15, quad3: m8..15/k8-15
    const int a_row = wm * 32 + (quad & 1) * 8 + lrow;   // + mi*16
    const int a_c8  = (quad >> 1);                       // column-half selector
    // B frag (two n8 tiles per ldsm.x4): quad0: n0..7/k0-7, quad1: n0..7/k8-15,
    //                                    quad2: n8..15/k0-7, quad3: n8..15/k8-15
    const int b_row = wn * 64 + (quad >> 1) * 8 + lrow;  // + p*16
    const int b_c8  = (quad & 1);

    // vocab tile range for this split: 393 = 6*44 + 3*43
    const int t0   = s * 43 + (s < 6 ? s : 6);
    const int tcnt = 43 + (s < 6 ? 1 : 0);

    float m_run[4], s_run[4];
#pragma unroll
    for (int i = 0; i < 4; i++) { m_run[i] = -3.0e38f; s_run[i] = 0.0f; }

#pragma unroll 1
    for (int ti = 0; ti < tcnt; ti++) {
        const int v0 = (t0 + ti) * 128;
        const __nv_bfloat16* Wt = &g_W[(size_t)v0 * NEMBD];

        float c[2][8][4];
#pragma unroll
        for (int mi = 0; mi < 2; mi++)
#pragma unroll
            for (int nj = 0; nj < 8; nj++)
#pragma unroll
                for (int e = 0; e < 4; e++) c[mi][nj][e] = 0.0f;

        // prologue: B chunks 0 and 1
#pragma unroll
        for (int pre = 0; pre < 2; pre++) {
            uint32_t bbase = smem_base + SMEM_B_OFF + pre * 16384;
#pragma unroll
            for (int j = 0; j < 4; j++) {
                int r = rb + j * 32;
                uint32_t bo = (uint32_t)r * 128u + (uint32_t)seg * 16u;
                cp_async16(bbase + swz(bo),
                           &Wt[(size_t)r * NEMBD + pre * 64 + seg * 8]);
            }
            cp_commit();
        }

#pragma unroll 1
        for (int kk = 0; kk < NCHUNK; kk++) {
            if (kk == NCHUNK - 1) cp_wait<0>(); else cp_wait<1>();
            __syncthreads();

            const uint32_t Ab = smem_base + SMEM_A_OFF + kk * 16384;
            const uint32_t Bb = smem_base + SMEM_B_OFF + (kk & 1) * 16384;

#pragma unroll
            for (int ks = 0; ks < 4; ks++) {
                const int kc = ks * 16;
                uint32_t a[2][4];
#pragma unroll
                for (int mi = 0; mi < 2; mi++) {
                    uint32_t bo = (uint32_t)(a_row + mi * 16) * 128u
                                + (uint32_t)(kc + a_c8 * 8) * 2u;
                    ldsm_x4(a[mi], Ab + swz(bo));
                }
                uint32_t b[4][4];
#pragma unroll
                for (int p = 0; p < 4; p++) {
                    uint32_t bo = (uint32_t)(b_row + p * 16) * 128u
                                + (uint32_t)(kc + b_c8 * 8) * 2u;
                    ldsm_x4(b[p], Bb + swz(bo));
                }
#pragma unroll
                for (int mi = 0; mi < 2; mi++)
#pragma unroll
                    for (int p = 0; p < 4; p++) {
                        mma16816(c[mi][p * 2 + 0], a[mi], &b[p][0]);
                        mma16816(c[mi][p * 2 + 1], a[mi], &b[p][2]);
                    }
            }
            __syncthreads();

            if (kk < NCHUNK - 2) {
                uint32_t bbase = smem_base + SMEM_B_OFF + (kk & 1) * 16384;
#pragma unroll
                for (int j = 0; j < 4; j++) {
                    int r = rb + j * 32;
                    uint32_t bo = (uint32_t)r * 128u + (uint32_t)seg * 16u;
                    cp_async16(bbase + swz(bo),
                               &Wt[(size_t)r * NEMBD + (kk + 2) * 64 + seg * 8]);
                }
                cp_commit();
            }
        }

        // ---- epilogue: online (max, sum-exp); accum layout:
        // c[mi][nj][e]: row = wm*32+mi*16+(e>>1)*8+(lane>>2); col = wn*64+nj*8+2*(lane&3)+(e&1)
        const bool edge = (v0 + 128 > VOCAB);
        const int colb = v0 + wn * 64 + 2 * (lane & 3);
#pragma unroll
        for (int sl = 0; sl < 4; sl++) {
            const int mi = sl >> 1, h = sl & 1;
            float tm = -3.0e38f;
#pragma unroll
            for (int nj = 0; nj < 8; nj++)
#pragma unroll
                for (int e = 0; e < 2; e++) {
                    float v = c[mi][nj][h * 2 + e];
                    if (edge && (colb + nj * 8 + e >= VOCAB)) v = -3.0e38f;
                    tm = fmaxf(tm, v);
                }
            tm = fmaxf(tm, __shfl_xor_sync(0xFFFFFFFFu, tm, 1));
            tm = fmaxf(tm, __shfl_xor_sync(0xFFFFFFFFu, tm, 2));
            float nm = fmaxf(m_run[sl], tm);
            float p = 0.0f;
#pragma unroll
            for (int nj = 0; nj < 8; nj++)
#pragma unroll
                for (int e = 0; e < 2; e++) {
                    float v = c[mi][nj][h * 2 + e];
                    if (edge && (colb + nj * 8 + e >= VOCAB)) v = -3.0e38f;
                    p += __expf(v - nm);
                }
            p += __shfl_xor_sync(0xFFFFFFFFu, p, 1);
            p += __shfl_xor_sync(0xFFFFFFFFu, p, 2);
            s_run[sl] = s_run[sl] * __expf(m_run[sl] - nm) + p;
            m_run[sl] = nm;
        }
    }

    // ---- store per-row partials, keyed by (s, wn) so the two column-half
    // warps covering the same rows never collide ----
    if ((lane & 3) == 0) {
#pragma unroll
        for (int sl = 0; sl < 4; sl++) {
            const int mi = sl >> 1, h = sl & 1;
            int row = m0 + wm * 32 + mi * 16 + h * 8 + (lane >> 2);
            g_pmax[s][wn][row] = m_run[sl];
            g_psum[s][wn][row] = s_run[sl];
        }
    }
}

// ---------------- kernel 4: label logits from the SAME bf16 operands ----------------
__global__ void label_logit_kernel(const int* __restrict__ label) {
    int wid = threadIdx.x >> 5, lid = threadIdx.x & 31;
    int row = blockIdx.x * 8 + wid;
    int lab = label[row];
    const __nv_bfloat162* xr = reinterpret_cast<const __nv_bfloat162*>(&g_X[(size_t)row * NEMBD]);
    const __nv_bfloat162* wr = reinterpret_cast<const __nv_bfloat162*>(&g_W[(size_t)lab * NEMBD]);
    float acc = 0.f;
#pragma unroll
    for (int it = 0; it < 12; it++) {
        __nv_bfloat162 x2 = xr[it * 32 + lid];
        __nv_bfloat162 w2 = wr[it * 32 + lid];
        acc += __bfloat162float(x2.x) * __bfloat162float(w2.x)
             + __bfloat162float(x2.y) * __bfloat162float(w2.y);
    }
#pragma unroll
    for (int o = 16; o; o >>= 1) acc += __shfl_xor_sync(0xFFFFFFFFu, acc, o);
    if (lid == 0) g_ll[row] = acc;
}

// ---------------- kernel 5: deterministic finalize ----------------
__global__ void finalize_kernel(float* __restrict__ out) {
    __shared__ float red[256];
    int t = threadIdx.x;
    float local = 0.f;
#pragma unroll 1
    for (int i = 0; i < NROWS / 256; i++) {
        int r = t + i * 256;
        float m = g_pmax[0][0][r];
#pragma unroll
        for (int s = 0; s < NSPLIT; s++) {
            m = fmaxf(m, g_pmax[s][0][r]);
            m = fmaxf(m, g_pmax[s][1][r]);
        }
        float S = 0.f;
#pragma unroll
        for (int s = 0; s < NSPLIT; s++) {
            S += g_psum[s][0][r] * __expf(g_pmax[s][0][r] - m);
            S += g_psum[s][1][r] * __expf(g_pmax[s][1][r] - m);
        }
        local += (m + logf(S)) - g_ll[r];
    }
    red[t] = local;
    __syncthreads();
    for (int off = 128; off; off >>= 1) {
        if (t < off) red[t] += red[t + off];
        __syncthreads();
    }
    if (t == 0) out[0] = red[0] * (1.0f / (float)NROWS);
}

// ---------------- launch ----------------
extern "C" void kernel_launch(void* const* d_in, const int* in_sizes, int n_in,
                              void* d_out, int out_size) {
    const int*   data  = (const int*)d_in[0];
    const int*   label = (const int*)d_in[1];
    const float* wte   = (const float*)d_in[2];
    const float* wpe   = (const float*)d_in[3];
    const float* W     = (const float*)d_in[4];
    float* out = (float*)d_out;

    cudaFuncSetAttribute(gemm_lse_kernel, cudaFuncAttributeMaxDynamicSharedMemorySize, SMEM_BYTES);

    prep_x_kernel<<<(NROWS * (NEMBD / 4)) / 256, 256>>>(data, wte, wpe);
    conv_w_kernel<<<(VPAD * (NEMBD / 4)) / 256, 256>>>(W);
    gemm_lse_kernel<<<dim3(NSPLIT, NROWS / 128), 256, SMEM_BYTES>>>();
    label_logit_kernel<<<NROWS / 8, 256>>>(label);
    finalize_kernel<<<1, 256>>>(out);
}

// round 4
// speedup vs baseline: 1.1627x; 1.1627x over previous
#include <cuda_runtime.h>
#include <cuda_bf16.h>
#include <cstdint>

#define VOCAB   50257
#define VPAD    50304        /* 393 * 128 */
#define NEMBD   768
#define NROWS   8192
#define SEQLEN  1024
#define NSPLIT  9
#define NCHUNK  12           /* 768 / 64 */

#define SMEM_A_OFF 0
#define SMEM_B_OFF (NCHUNK * 16384)             /* 196608 */
#define SMEM_BYTES (SMEM_B_OFF + 2 * 16384)     /* 229376 */

// ---------------- device scratch ----------------
__device__ __align__(256) __nv_bfloat16 g_X[(size_t)NROWS * NEMBD];   // gelu(wte+wpe), bf16
__device__ __align__(256) __nv_bfloat16 g_W[(size_t)VPAD * NEMBD];    // W bf16, zero-padded
__device__ float g_pmax[NSPLIT][2][NROWS];
__device__ float g_psum[NSPLIT][2][NROWS];
__device__ float g_ll[NROWS];
__device__ float g_row[NROWS];

// ---------------- helpers ----------------
__device__ __forceinline__ uint32_t smem_u32(const void* p) {
    uint32_t a;
    asm("{ .reg .u64 t; cvta.to.shared.u64 t, %1; cvt.u32.u64 %0, t; }" : "=r"(a) : "l"(p));
    return a;
}
__device__ __forceinline__ void cp_async16(uint32_t dst, const void* src) {
    asm volatile("cp.async.cg.shared.global [%0], [%1], 16;" :: "r"(dst), "l"(src));
}
__device__ __forceinline__ void cp_commit() {
    asm volatile("cp.async.commit_group;" ::: "memory");
}
template <int N>
__device__ __forceinline__ void cp_wait() {
    asm volatile("cp.async.wait_group %0;" :: "n"(N) : "memory");
}
__device__ __forceinline__ void ldsm_x4(uint32_t (&r)[4], uint32_t addr) {
    asm volatile("ldmatrix.sync.aligned.m8n8.x4.shared.b16 {%0,%1,%2,%3}, [%4];"
                 : "=r"(r[0]), "=r"(r[1]), "=r"(r[2]), "=r"(r[3]) : "r"(addr));
}
__device__ __forceinline__ void mma16816(float* c, const uint32_t* a, const uint32_t* b) {
    asm volatile(
        "mma.sync.aligned.m16n8k16.row.col.f32.bf16.bf16.f32 "
        "{%0,%1,%2,%3}, {%4,%5,%6,%7}, {%8,%9}, {%0,%1,%2,%3};"
        : "+f"(c[0]), "+f"(c[1]), "+f"(c[2]), "+f"(c[3])
        : "r"(a[0]), "r"(a[1]), "r"(a[2]), "r"(a[3]), "r"(b[0]), "r"(b[1]));
}
__device__ __forceinline__ uint32_t swz(uint32_t bo) { return bo ^ ((bo >> 3) & 0x70u); }

// ---------------- kernel 1: x = gelu(wte[tok] + wpe[pos]) -> bf16 ----------------
__global__ void prep_x_kernel(const int* __restrict__ data, const float* __restrict__ wte,
                              const float* __restrict__ wpe) {
    int idx = blockIdx.x * blockDim.x + threadIdx.x;
    if (idx >= NROWS * (NEMBD / 4)) return;
    int row = idx / (NEMBD / 4);
    int c4  = idx % (NEMBD / 4);
    int tok = data[row];
    int pos = row & (SEQLEN - 1);
    float4 a = *reinterpret_cast<const float4*>(wte + (size_t)tok * NEMBD + c4 * 4);
    float4 p = *reinterpret_cast<const float4*>(wpe + (size_t)pos * NEMBD + c4 * 4);
    const float K0 = 0.7978845608028654f, K1 = 0.044715f;
    float v[4] = {a.x + p.x, a.y + p.y, a.z + p.z, a.w + p.w};
    float g[4];
#pragma unroll
    for (int i = 0; i < 4; i++) {
        float x = v[i];
        g[i] = 0.5f * x * (1.0f + tanhf(K0 * (x + K1 * x * x * x)));
    }
    __nv_bfloat162* dst = reinterpret_cast<__nv_bfloat162*>(&g_X[(size_t)row * NEMBD + c4 * 4]);
    dst[0] = __floats2bfloat162_rn(g[0], g[1]);
    dst[1] = __floats2bfloat162_rn(g[2], g[3]);
}

// ---------------- kernel 2: W fp32 -> bf16 (zero-padded rows) ----------------
__global__ void conv_w_kernel(const float* __restrict__ W) {
    int idx = blockIdx.x * blockDim.x + threadIdx.x;
    if (idx >= VPAD * (NEMBD / 4)) return;
    int v  = idx / (NEMBD / 4);
    int c4 = idx % (NEMBD / 4);
    __nv_bfloat162 r0, r1;
    if (v < VOCAB) {
        float4 w = *reinterpret_cast<const float4*>(W + (size_t)v * NEMBD + c4 * 4);
        r0 = __floats2bfloat162_rn(w.x, w.y);
        r1 = __floats2bfloat162_rn(w.z, w.w);
    } else {
        r0 = __floats2bfloat162_rn(0.f, 0.f);
        r1 = r0;
    }
    __nv_bfloat162* dst = reinterpret_cast<__nv_bfloat162*>(&g_W[(size_t)v * NEMBD + c4 * 4]);
    dst[0] = r0;
    dst[1] = r1;
}

// ---------------- kernel 3: fused GEMM (mma.sync) + online logsumexp ----------------
// 256 threads = 8 warps (4M x 2N); warp tile 32x64; CTA tile 128x128.
// A (128x768) resident in SMEM. B streamed as one continuous chunk sequence across
// all vocab tiles: S=2 buffers, ONE __syncthreads per chunk, prefetch for chunk g+1
// issued between ks=0 LDSMs and the MMA wall of chunk g (targets the buffer last
// read in chunk g-1 -> race-free under the top-of-chunk barrier).
__global__ void __launch_bounds__(256, 1)
gemm_lse_kernel() {
    extern __shared__ char smem[];
    const uint32_t smem_base = smem_u32(smem);
    const int tid  = threadIdx.x;
    const int lane = tid & 31;
    const int wid  = tid >> 5;
    const int wm   = wid >> 1;
    const int wn   = wid & 1;
    const int s    = blockIdx.x;
    const int m0   = blockIdx.y * 128;

    const int rb  = tid >> 3;           // 0..31
    const int seg = tid & 7;            // 0..7
    const uint32_t cpo = swz((uint32_t)rb * 128u + (uint32_t)seg * 16u);   // cp.async smem offset (j=0)
    const uint32_t cpo1 = swz((uint32_t)(rb + 32) * 128u + (uint32_t)seg * 16u);
    const uint32_t cpo2 = swz((uint32_t)(rb + 64) * 128u + (uint32_t)seg * 16u);
    const uint32_t cpo3 = swz((uint32_t)(rb + 96) * 128u + (uint32_t)seg * 16u);

    // ---- resident A: 12 chunks of 128x64 bf16 (group) ----
#pragma unroll 1
    for (int kk = 0; kk < NCHUNK; kk++) {
        uint32_t abase = smem_base + SMEM_A_OFF + kk * 16384;
        const __nv_bfloat16* src = &g_X[(size_t)(m0 + rb) * NEMBD + kk * 64 + seg * 8];
        cp_async16(abase + cpo,  src);
        cp_async16(abase + cpo1, src + 32 * NEMBD);
        cp_async16(abase + cpo2, src + 64 * NEMBD);
        cp_async16(abase + cpo3, src + 96 * NEMBD);
    }
    cp_commit();

    // vocab tile range: 393 = 6*44 + 3*43
    const int t0   = s * 43 + (s < 6 ? s : 6);
    const int tcnt = 43 + (s < 6 ? 1 : 0);
    const int NC   = tcnt * NCHUNK;

    // ---- B chunk 0 into buf0 (group) ----
    {
        uint32_t bbase = smem_base + SMEM_B_OFF;
        const __nv_bfloat16* src = &g_W[(size_t)(t0 * 128 + rb) * NEMBD + seg * 8];
        cp_async16(bbase + cpo,  src);
        cp_async16(bbase + cpo1, src + 32 * NEMBD);
        cp_async16(bbase + cpo2, src + 64 * NEMBD);
        cp_async16(bbase + cpo3, src + 96 * NEMBD);
    }
    cp_commit();

    // ---- ldmatrix lane constants ----
    const int quad = lane >> 3;
    const int lrow = lane & 7;
    const int a_row = wm * 32 + (quad & 1) * 8 + lrow;
    const int a_c8  = (quad >> 1);
    const int b_row = wn * 64 + (quad >> 1) * 8 + lrow;
    const int b_c8  = (quad & 1);

    float m_run[4], s_run[4];
#pragma unroll
    for (int i = 0; i < 4; i++) { m_run[i] = -3.0e38f; s_run[i] = 0.0f; }

    float c[2][8][4];
#pragma unroll
    for (int mi = 0; mi < 2; mi++)
#pragma unroll
        for (int nj = 0; nj < 8; nj++)
#pragma unroll
            for (int e = 0; e < 4; e++) c[mi][nj][e] = 0.0f;

    int v0 = t0 * 128;      // current tile vocab base
    int kk = 0;             // chunk within tile
    int vp = t0 * 128;      // prefetch tile vocab base (chunk g+1)
    int kp = 1;             // prefetch chunk-in-tile

#pragma unroll 1
    for (int g = 0; g < NC; g++) {
        cp_wait<0>();
        __syncthreads();

        const uint32_t Ab = smem_base + SMEM_A_OFF + kk * 16384;
        const uint32_t Bb = smem_base + SMEM_B_OFF + (g & 1) * 16384;

        // ks = 0 LDSMs first, then prefetch, then the MMA wall
        uint32_t a0[2][4], b0[4][4];
#pragma unroll
        for (int mi = 0; mi < 2; mi++) {
            uint32_t bo = (uint32_t)(a_row + mi * 16) * 128u + (uint32_t)(a_c8 * 8) * 2u;
            ldsm_x4(a0[mi], Ab + swz(bo));
        }
#pragma unroll
        for (int p = 0; p < 4; p++) {
            uint32_t bo = (uint32_t)(b_row + p * 16) * 128u + (uint32_t)(b_c8 * 8) * 2u;
            ldsm_x4(b0[p], Bb + swz(bo));
        }

        if (g + 1 < NC) {   // prefetch chunk g+1 into the buffer last read at g-1
            uint32_t bbase = smem_base + SMEM_B_OFF + ((g + 1) & 1) * 16384;
            const __nv_bfloat16* src = &g_W[(size_t)(vp + rb) * NEMBD + kp * 64 + seg * 8];
            cp_async16(bbase + cpo,  src);
            cp_async16(bbase + cpo1, src + 32 * NEMBD);
            cp_async16(bbase + cpo2, src + 64 * NEMBD);
            cp_async16(bbase + cpo3, src + 96 * NEMBD);
        }
        cp_commit();
        kp++;
        if (kp == NCHUNK) { kp = 0; vp += 128; }

#pragma unroll
        for (int mi = 0; mi < 2; mi++)
#pragma unroll
            for (int p = 0; p < 4; p++) {
                mma16816(c[mi][p * 2 + 0], a0[mi], &b0[p][0]);
                mma16816(c[mi][p * 2 + 1], a0[mi], &b0[p][2]);
            }

#pragma unroll
        for (int ks = 1; ks < 4; ks++) {
            const int kc = ks * 16;
            uint32_t a[2][4], b[4][4];
#pragma unroll
            for (int mi = 0; mi < 2; mi++) {
                uint32_t bo = (uint32_t)(a_row + mi * 16) * 128u
                            + (uint32_t)(kc + a_c8 * 8) * 2u;
                ldsm_x4(a[mi], Ab + swz(bo));
            }
#pragma unroll
            for (int p = 0; p < 4; p++) {
                uint32_t bo = (uint32_t)(b_row + p * 16) * 128u
                            + (uint32_t)(kc + b_c8 * 8) * 2u;
                ldsm_x4(b[p], Bb + swz(bo));
            }
#pragma unroll
            for (int mi = 0; mi < 2; mi++)
#pragma unroll
                for (int p = 0; p < 4; p++) {
                    mma16816(c[mi][p * 2 + 0], a[mi], &b[p][0]);
                    mma16816(c[mi][p * 2 + 1], a[mi], &b[p][2]);
                }
        }

        kk++;
        if (kk == NCHUNK) {
            // ---- tile epilogue (registers only; overlaps the in-flight prefetch) ----
            kk = 0;
            const bool edge = (v0 + 128 > VOCAB);
            const int colb = v0 + wn * 64 + 2 * (lane & 3);
            if (!edge) {
#pragma unroll
                for (int sl = 0; sl < 4; sl++) {
                    const int mi = sl >> 1, h = sl & 1;
                    float tm = -3.0e38f;
#pragma unroll
                    for (int nj = 0; nj < 8; nj++) {
                        tm = fmaxf(tm, c[mi][nj][h * 2 + 0]);
                        tm = fmaxf(tm, c[mi][nj][h * 2 + 1]);
                    }
                    tm = fmaxf(tm, __shfl_xor_sync(0xFFFFFFFFu, tm, 1));
                    tm = fmaxf(tm, __shfl_xor_sync(0xFFFFFFFFu, tm, 2));
                    float nm = fmaxf(m_run[sl], tm);
                    float p = 0.0f;
#pragma unroll
                    for (int nj = 0; nj < 8; nj++) {
                        p += __expf(c[mi][nj][h * 2 + 0] - nm);
                        p += __expf(c[mi][nj][h * 2 + 1] - nm);
                    }
                    p += __shfl_xor_sync(0xFFFFFFFFu, p, 1);
                    p += __shfl_xor_sync(0xFFFFFFFFu, p, 2);
                    s_run[sl] = s_run[sl] * __expf(m_run[sl] - nm) + p;
                    m_run[sl] = nm;
                }
            } else {
#pragma unroll
                for (int sl = 0; sl < 4; sl++) {
                    const int mi = sl >> 1, h = sl & 1;
                    float tm = -3.0e38f;
#pragma unroll
                    for (int nj = 0; nj < 8; nj++)
#pragma unroll
                        for (int e = 0; e < 2; e++) {
                            float v = c[mi][nj][h * 2 + e];
                            if (colb + nj * 8 + e >= VOCAB) v = -3.0e38f;
                            tm = fmaxf(tm, v);
                        }
                    tm = fmaxf(tm, __shfl_xor_sync(0xFFFFFFFFu, tm, 1));
                    tm = fmaxf(tm, __shfl_xor_sync(0xFFFFFFFFu, tm, 2));
                    float nm = fmaxf(m_run[sl], tm);
                    float p = 0.0f;
#pragma unroll
                    for (int nj = 0; nj < 8; nj++)
#pragma unroll
                        for (int e = 0; e < 2; e++) {
                            float v = c[mi][nj][h * 2 + e];
                            if (colb + nj * 8 + e >= VOCAB) v = -3.0e38f;
                            p += __expf(v - nm);
                        }
                    p += __shfl_xor_sync(0xFFFFFFFFu, p, 1);
                    p += __shfl_xor_sync(0xFFFFFFFFu, p, 2);
                    s_run[sl] = s_run[sl] * __expf(m_run[sl] - nm) + p;
                    m_run[sl] = nm;
                }
            }
            v0 += 128;
#pragma unroll
            for (int mi = 0; mi < 2; mi++)
#pragma unroll
                for (int nj = 0; nj < 8; nj++)
#pragma unroll
                    for (int e = 0; e < 4; e++) c[mi][nj][e] = 0.0f;
        }
    }

    // ---- store per-row partials keyed by (s, wn) ----
    if ((lane & 3) == 0) {
#pragma unroll
        for (int sl = 0; sl < 4; sl++) {
            const int mi = sl >> 1, h = sl & 1;
            int row = m0 + wm * 32 + mi * 16 + h * 8 + (lane >> 2);
            g_pmax[s][wn][row] = m_run[sl];
            g_psum[s][wn][row] = s_run[sl];
        }
    }
}

// ---------------- kernel 4: label logits ----------------
__global__ void label_logit_kernel(const int* __restrict__ label) {
    int wid = threadIdx.x >> 5, lid = threadIdx.x & 31;
    int row = blockIdx.x * 8 + wid;
    int lab = label[row];
    const __nv_bfloat162* xr = reinterpret_cast<const __nv_bfloat162*>(&g_X[(size_t)row * NEMBD]);
    const __nv_bfloat162* wr = reinterpret_cast<const __nv_bfloat162*>(&g_W[(size_t)lab * NEMBD]);
    float acc = 0.f;
#pragma unroll
    for (int it = 0; it < 12; it++) {
        __nv_bfloat162 x2 = xr[it * 32 + lid];
        __nv_bfloat162 w2 = wr[it * 32 + lid];
        acc += __bfloat162float(x2.x) * __bfloat162float(w2.x)
             + __bfloat162float(x2.y) * __bfloat162float(w2.y);
    }
#pragma unroll
    for (int o = 16; o; o >>= 1) acc += __shfl_xor_sync(0xFFFFFFFFu, acc, o);
    if (lid == 0) g_ll[row] = acc;
}

// ---------------- kernel 5a: per-row NLL (parallel) ----------------
__global__ void rownll_kernel() {
    int r = blockIdx.x * 256 + threadIdx.x;
    float m = g_pmax[0][0][r];
#pragma unroll
    for (int s = 0; s < NSPLIT; s++) {
        m = fmaxf(m, g_pmax[s][0][r]);
        m = fmaxf(m, g_pmax[s][1][r]);
    }
    float S = 0.f;
#pragma unroll
    for (int s = 0; s < NSPLIT; s++) {
        S += g_psum[s][0][r] * __expf(g_pmax[s][0][r] - m);
        S += g_psum[s][1][r] * __expf(g_pmax[s][1][r] - m);
    }
    g_row[r] = (m + logf(S)) - g_ll[r];
}

// ---------------- kernel 5b: deterministic mean ----------------
__global__ void reduce_kernel(float* __restrict__ out) {
    __shared__ float red[256];
    int t = threadIdx.x;
    float local = 0.f;
#pragma unroll
    for (int i = 0; i < NROWS / 256; i++) local += g_row[t + i * 256];
    red[t] = local;
    __syncthreads();
    for (int off = 128; off; off >>= 1) {
        if (t < off) red[t] += red[t + off];
        __syncthreads();
    }
    if (t == 0) out[0] = red[0] * (1.0f / (float)NROWS);
}

// ---------------- launch ----------------
extern "C" void kernel_launch(void* const* d_in, const int* in_sizes, int n_in,
                              void* d_out, int out_size) {
    const int*   data  = (const int*)d_in[0];
    const int*   label = (const int*)d_in[1];
    const float* wte   = (const float*)d_in[2];
    const float* wpe   = (const float*)d_in[3];
    const float* W     = (const float*)d_in[4];
    float* out = (float*)d_out;

    cudaFuncSetAttribute(gemm_lse_kernel, cudaFuncAttributeMaxDynamicSharedMemorySize, SMEM_BYTES);

    prep_x_kernel<<<(NROWS * (NEMBD / 4)) / 256, 256>>>(data, wte, wpe);
    conv_w_kernel<<<(VPAD * (NEMBD / 4)) / 256, 256>>>(W);
    gemm_lse_kernel<<<dim3(NSPLIT, NROWS / 128), 256, SMEM_BYTES>>>();
    label_logit_kernel<<<NROWS / 8, 256>>>(label);
    rownll_kernel<<<NROWS / 256, 256>>>();
    reduce_kernel<<<1, 256>>>(out);
}